// round 1
// baseline (speedup 1.0000x reference)
#include <cuda_runtime.h>
#include <cuda_bf16.h>
#include <cstdint>

#define N_NODES 50000
#define N_EDGES 800000
#define HIDDEN  128
#define N_LAYERS 3
#define N_GRAPHS 512
#define LN_EPS 1e-5f

// ---------------- scratch (device globals; no allocation allowed) ----------
__device__ float g_x0[N_NODES * HIDDEN];            // embedding output
__device__ float g_h0[N_NODES * HIDDEN];            // x + agg
__device__ float g_h1[N_NODES * HIDDEN];            // after first MLP
__device__ float g_xcat[N_NODES * 3 * HIDDEN];      // JK concat (layer outputs)
__device__ int   g_counts[N_NODES];
__device__ int   g_rowstart[N_NODES + 1];
__device__ int   g_cursor[N_NODES];
__device__ int   g_srcsorted[N_EDGES];
__device__ int   g_gstart[N_GRAPHS + 1];
__device__ float g_pooled[N_GRAPHS * 3 * HIDDEN];

// ---------------- small helpers -------------------------------------------
__device__ __forceinline__ unsigned long long pack2(float a, float b) {
    unsigned long long r;
    asm("mov.b64 %0, {%1, %2};" : "=l"(r) : "f"(a), "f"(b));
    return r;
}
__device__ __forceinline__ void unpack2(unsigned long long v, float& lo, float& hi) {
    asm("mov.b64 {%0, %1}, %2;" : "=f"(lo), "=f"(hi) : "l"(v));
}
__device__ __forceinline__ void fma2(unsigned long long& d, unsigned long long a,
                                     unsigned long long b) {
    asm("fma.rn.f32x2 %0, %1, %2, %0;" : "+l"(d) : "l"(a), "l"(b));
}

// ---------------- 1) embedding gather -------------------------------------
__global__ void embed_kernel(const int* __restrict__ z, const float4* __restrict__ table) {
    int idx = blockIdx.x * blockDim.x + threadIdx.x;   // over N_NODES*32 float4
    if (idx >= N_NODES * 32) return;
    int node = idx >> 5, c = idx & 31;
    ((float4*)g_x0)[idx] = table[z[node] * 32 + c];
}

// ---------------- 2) CSR build --------------------------------------------
__global__ void zero_counts_kernel() {
    int i = blockIdx.x * blockDim.x + threadIdx.x;
    if (i < N_NODES) g_counts[i] = 0;
}

__global__ void count_kernel(const int* __restrict__ dst) {
    int e = blockIdx.x * blockDim.x + threadIdx.x;
    if (e < N_EDGES) atomicAdd(&g_counts[dst[e]], 1);
}

__global__ void scan_kernel() {   // single block, 1024 threads
    __shared__ int sdata[1024];
    __shared__ int s_running;
    int tid = threadIdx.x;
    if (tid == 0) s_running = 0;
    __syncthreads();
    for (int base = 0; base < N_NODES; base += 1024) {
        int i = base + tid;
        int v = (i < N_NODES) ? g_counts[i] : 0;
        sdata[tid] = v;
        __syncthreads();
        for (int off = 1; off < 1024; off <<= 1) {
            int t = (tid >= off) ? sdata[tid - off] : 0;
            __syncthreads();
            sdata[tid] += t;
            __syncthreads();
        }
        int incl = sdata[tid];
        int total = sdata[1023];
        int run = s_running;
        if (i < N_NODES) {
            int excl = run + incl - v;
            g_rowstart[i] = excl;
            g_cursor[i]   = excl;
        }
        __syncthreads();
        if (tid == 0) s_running = run + total;
        __syncthreads();
    }
    if (tid == 0) g_rowstart[N_NODES] = s_running;
}

__global__ void place_kernel(const int* __restrict__ src, const int* __restrict__ dst) {
    int e = blockIdx.x * blockDim.x + threadIdx.x;
    if (e >= N_EDGES) return;
    int d = dst[e];
    int p = atomicAdd(&g_cursor[d], 1);
    g_srcsorted[p] = src[e];
}

// ---------------- 3) neighbor aggregation: h0 = x + sum x[src] ------------
__global__ void agg_kernel(int layer) {
    const float4* xin;
    int stride4;
    if (layer == 0) { xin = (const float4*)g_x0; stride4 = 32; }
    else            { xin = (const float4*)(g_xcat + (layer - 1) * HIDDEN); stride4 = 96; }
    int warp = threadIdx.x >> 5, lane = threadIdx.x & 31;
    int node = blockIdx.x * 4 + warp;
    if (node >= N_NODES) return;
    float4 acc = xin[(long)node * stride4 + lane];
    int s = g_rowstart[node], e = g_rowstart[node + 1];
    for (int j = s; j < e; j++) {
        int u = g_srcsorted[j];
        float4 v = xin[(long)u * stride4 + lane];
        acc.x += v.x; acc.y += v.y; acc.z += v.z; acc.w += v.w;
    }
    ((float4*)g_h0)[node * 32 + lane] = acc;
}

// ---------------- 4) fused GEMM (+bias,+relu[,+LN]) -----------------------
// MODE 0: g_h1 = relu(g_h0 @ W + b)
// MODE 1: xcat[:, l*128:(l+1)*128] = LN(relu(g_h1 @ W + b))
template <int MODE>
__global__ __launch_bounds__(256) void gemm_kernel(int layer,
                                                   const float* __restrict__ Wg,
                                                   const float* __restrict__ bg,
                                                   const float* __restrict__ lng,
                                                   const float* __restrict__ lnb) {
    extern __shared__ float sm[];
    float* Wsm = sm;                    // 128*128 floats (64 KB)
    float* Asm = sm + 128 * 128;        // 64*128 floats  (32 KB)
    const float* A = (MODE == 0) ? g_h0 : g_h1;

    int tid = threadIdx.x;
    int row0 = blockIdx.x * 64;

    const float4* W4 = (const float4*)Wg;
    float4* Wsm4 = (float4*)Wsm;
#pragma unroll
    for (int i = tid; i < 4096; i += 256) Wsm4[i] = W4[i];

    const float4* A4 = (const float4*)A;
    float4* Asm4 = (float4*)Asm;
#pragma unroll
    for (int i = tid; i < 2048; i += 256) {
        int r = i >> 5, c = i & 31;
        int gr = row0 + r;
        Asm4[i] = (gr < N_NODES) ? A4[gr * 32 + c] : make_float4(0.f, 0.f, 0.f, 0.f);
    }
    __syncthreads();

    int tx = tid & 31, ty = tid >> 5;
    float4 bv = ((const float4*)bg)[tx];
    unsigned long long acc[16];
#pragma unroll
    for (int r = 0; r < 8; r++) {
        acc[2 * r]     = pack2(bv.x, bv.y);
        acc[2 * r + 1] = pack2(bv.z, bv.w);
    }
    const ulonglong2* Wsm2 = (const ulonglong2*)Wsm;
    const float* Arow = Asm + ty * 8 * 128;

#pragma unroll 8
    for (int k = 0; k < 128; k++) {
        ulonglong2 w = Wsm2[k * 32 + tx];
#pragma unroll
        for (int r = 0; r < 8; r++) {
            float a = Arow[r * 128 + k];
            unsigned long long a2 = pack2(a, a);
            fma2(acc[2 * r],     a2, w.x);
            fma2(acc[2 * r + 1], a2, w.y);
        }
    }

    if (MODE == 0) {
#pragma unroll
        for (int r = 0; r < 8; r++) {
            int row = row0 + ty * 8 + r;
            if (row >= N_NODES) continue;
            float v0, v1, v2, v3;
            unpack2(acc[2 * r], v0, v1);
            unpack2(acc[2 * r + 1], v2, v3);
            v0 = fmaxf(v0, 0.f); v1 = fmaxf(v1, 0.f);
            v2 = fmaxf(v2, 0.f); v3 = fmaxf(v3, 0.f);
            ((float4*)g_h1)[row * 32 + tx] = make_float4(v0, v1, v2, v3);
        }
    } else {
        float4 gv  = ((const float4*)lng)[tx];
        float4 bbv = ((const float4*)lnb)[tx];
#pragma unroll
        for (int r = 0; r < 8; r++) {
            float v0, v1, v2, v3;
            unpack2(acc[2 * r], v0, v1);
            unpack2(acc[2 * r + 1], v2, v3);
            v0 = fmaxf(v0, 0.f); v1 = fmaxf(v1, 0.f);
            v2 = fmaxf(v2, 0.f); v3 = fmaxf(v3, 0.f);
            float s = v0 + v1 + v2 + v3;
#pragma unroll
            for (int o = 16; o > 0; o >>= 1) s += __shfl_xor_sync(0xffffffffu, s, o);
            float mu = s * (1.f / 128.f);
            float d0 = v0 - mu, d1 = v1 - mu, d2 = v2 - mu, d3 = v3 - mu;
            float q = d0 * d0 + d1 * d1 + d2 * d2 + d3 * d3;
#pragma unroll
            for (int o = 16; o > 0; o >>= 1) q += __shfl_xor_sync(0xffffffffu, q, o);
            float rs = rsqrtf(q * (1.f / 128.f) + LN_EPS);
            float o0 = gv.x * d0 * rs + bbv.x;
            float o1 = gv.y * d1 * rs + bbv.y;
            float o2 = gv.z * d2 * rs + bbv.z;
            float o3 = gv.w * d3 * rs + bbv.w;
            int row = row0 + ty * 8 + r;
            if (row < N_NODES)
                ((float4*)g_xcat)[row * 96 + layer * 32 + tx] = make_float4(o0, o1, o2, o3);
        }
    }
}

// ---------------- 5) graph boundaries + mean pool -------------------------
__global__ void gstart_kernel(const int* __restrict__ batch) {
    int g = blockIdx.x * blockDim.x + threadIdx.x;
    if (g > N_GRAPHS) return;
    if (g == N_GRAPHS) { g_gstart[N_GRAPHS] = N_NODES; return; }
    int lo = 0, hi = N_NODES;
    while (lo < hi) {
        int mid = (lo + hi) >> 1;
        if (batch[mid] < g) lo = mid + 1; else hi = mid;
    }
    g_gstart[g] = lo;
}

__global__ void pool_kernel() {
    int g = blockIdx.x, t = threadIdx.x;   // 128 threads
    int s = g_gstart[g], e = g_gstart[g + 1];
    float a0 = 0.f, a1 = 0.f, a2 = 0.f;
    for (int n = s; n < e; n++) {
        const float* r = g_xcat + (long)n * 384;
        a0 += r[t]; a1 += r[128 + t]; a2 += r[256 + t];
    }
    float inv = 1.f / fmaxf((float)(e - s), 1.f);
    g_pooled[g * 384 + t]       = a0 * inv;
    g_pooled[g * 384 + 128 + t] = a1 * inv;
    g_pooled[g * 384 + 256 + t] = a2 * inv;
}

// ---------------- 6) MLP head ---------------------------------------------
__global__ void head_kernel(const float* __restrict__ l1W, const float* __restrict__ l1b,
                            const float* __restrict__ l2W, const float* __restrict__ l2b,
                            float* __restrict__ out) {
    __shared__ float prow[384];
    __shared__ float red[128];
    int g = blockIdx.x, t = threadIdx.x;   // 128 threads
    for (int i = t; i < 384; i += 128) prow[i] = g_pooled[g * 384 + i];
    __syncthreads();
    float s = l1b[t];
#pragma unroll 8
    for (int k = 0; k < 384; k++) s += prow[k] * l1W[k * 128 + t];
    s = fmaxf(s, 0.f);
    red[t] = s * l2W[t];
    __syncthreads();
    for (int off = 64; off > 0; off >>= 1) {
        if (t < off) red[t] += red[t + off];
        __syncthreads();
    }
    if (t == 0) out[g] = red[0] + l2b[0];
}

// ---------------- launch ---------------------------------------------------
extern "C" void kernel_launch(void* const* d_in, const int* in_sizes, int n_in,
                              void* d_out, int out_size) {
    const int*   z     = (const int*)d_in[0];
    const int*   ei    = (const int*)d_in[1];
    const int*   src   = ei;
    const int*   dst   = ei + N_EDGES;
    const int*   batch = (const int*)d_in[2];
    const float* ztab  = (const float*)d_in[3];
    const float* W1    = (const float*)d_in[4];
    const float* b1    = (const float*)d_in[5];
    const float* W2    = (const float*)d_in[6];
    const float* b2    = (const float*)d_in[7];
    const float* lng   = (const float*)d_in[8];
    const float* lnb   = (const float*)d_in[9];
    const float* l1W   = (const float*)d_in[10];
    const float* l1b   = (const float*)d_in[11];
    const float* l2W   = (const float*)d_in[12];
    const float* l2b   = (const float*)d_in[13];
    float* out = (float*)d_out;

    const int SMEM = 98304;  // 96 KB dynamic
    cudaFuncSetAttribute(gemm_kernel<0>, cudaFuncAttributeMaxDynamicSharedMemorySize, SMEM);
    cudaFuncSetAttribute(gemm_kernel<1>, cudaFuncAttributeMaxDynamicSharedMemorySize, SMEM);

    // embedding + CSR build
    embed_kernel<<<(N_NODES * 32 + 255) / 256, 256>>>(z, (const float4*)ztab);
    zero_counts_kernel<<<(N_NODES + 255) / 256, 256>>>();
    count_kernel<<<(N_EDGES + 255) / 256, 256>>>(dst);
    scan_kernel<<<1, 1024>>>();
    place_kernel<<<(N_EDGES + 255) / 256, 256>>>(src, dst);

    const int GEMM_BLKS = (N_NODES + 63) / 64;
    for (int l = 0; l < N_LAYERS; l++) {
        agg_kernel<<<(N_NODES + 3) / 4, 128>>>(l);
        gemm_kernel<0><<<GEMM_BLKS, 256, SMEM>>>(l, W1 + l * 128 * 128, b1 + l * 128,
                                                 nullptr, nullptr);
        gemm_kernel<1><<<GEMM_BLKS, 256, SMEM>>>(l, W2 + l * 128 * 128, b2 + l * 128,
                                                 lng + l * 128, lnb + l * 128);
    }

    gstart_kernel<<<3, 256>>>(batch);
    pool_kernel<<<N_GRAPHS, 128>>>();
    head_kernel<<<N_GRAPHS, 128>>>(l1W, l1b, l2W, l2b, out);
}

// round 3
// speedup vs baseline: 1.1620x; 1.1620x over previous
#include <cuda_runtime.h>
#include <cuda_bf16.h>
#include <cstdint>

#define N_NODES 50000
#define N_EDGES 800000
#define HIDDEN  128
#define N_LAYERS 3
#define N_GRAPHS 512
#define LN_EPS 1e-5f
#define SCAN_BLOCKS 49   // ceil(50000/1024)

// ---------------- scratch (device globals; no allocation allowed) ----------
__device__ float g_x0[N_NODES * HIDDEN];
__device__ float g_h0[N_NODES * HIDDEN];
__device__ float g_h1[N_NODES * HIDDEN];
__device__ float g_xcat[N_NODES * 3 * HIDDEN];
__device__ int   g_counts[N_NODES];
__device__ int   g_rowstart[N_NODES + 1];
__device__ int   g_cursor[N_NODES];        // reused as block-local scan temp
__device__ int   g_srcsorted[N_EDGES];
__device__ int   g_blocksum[64];
__device__ int   g_blockoff[64];
__device__ int   g_gstart[N_GRAPHS + 1];
__device__ float g_pooled[N_GRAPHS * 3 * HIDDEN];

// ---------------- small helpers -------------------------------------------
__device__ __forceinline__ unsigned long long pack2(float a, float b) {
    unsigned long long r;
    asm("mov.b64 %0, {%1, %2};" : "=l"(r) : "f"(a), "f"(b));
    return r;
}
__device__ __forceinline__ void unpack2(unsigned long long v, float& lo, float& hi) {
    asm("mov.b64 {%0, %1}, %2;" : "=f"(lo), "=f"(hi) : "l"(v));
}
__device__ __forceinline__ void fma2(unsigned long long& d, unsigned long long a,
                                     unsigned long long b) {
    asm("fma.rn.f32x2 %0, %1, %2, %0;" : "+l"(d) : "l"(a), "l"(b));
}

// ---------------- 1) embedding gather -------------------------------------
__global__ void embed_kernel(const int* __restrict__ z, const float4* __restrict__ table) {
    int idx = blockIdx.x * blockDim.x + threadIdx.x;
    if (idx >= N_NODES * 32) return;
    int node = idx >> 5, c = idx & 31;
    ((float4*)g_x0)[idx] = table[z[node] * 32 + c];
}

// ---------------- 2) CSR build --------------------------------------------
__global__ void zero_counts_kernel() {
    int i = blockIdx.x * blockDim.x + threadIdx.x;
    if (i < N_NODES) g_counts[i] = 0;
}

__global__ void count_kernel(const int* __restrict__ dst) {
    int e = blockIdx.x * blockDim.x + threadIdx.x;
    if (e < N_EDGES) atomicAdd(&g_counts[dst[e]], 1);
}

// block-level scan: writes block-local EXCLUSIVE scan into g_cursor,
// per-block total into g_blocksum.
__global__ __launch_bounds__(1024) void scan1_kernel() {
    __shared__ int wsum[32];
    int tid = threadIdx.x, b = blockIdx.x;
    int i = b * 1024 + tid;
    int lane = tid & 31, w = tid >> 5;
    int v = (i < N_NODES) ? g_counts[i] : 0;
    int x = v;
#pragma unroll
    for (int off = 1; off < 32; off <<= 1) {
        int t = __shfl_up_sync(0xffffffffu, x, off);
        if (lane >= off) x += t;
    }
    if (lane == 31) wsum[w] = x;
    __syncthreads();
    if (w == 0) {
        int y = wsum[lane];
#pragma unroll
        for (int off = 1; off < 32; off <<= 1) {
            int t = __shfl_up_sync(0xffffffffu, y, off);
            if (lane >= off) y += t;
        }
        wsum[lane] = y;
    }
    __syncthreads();
    int incl = x + (w > 0 ? wsum[w - 1] : 0);
    if (i < N_NODES) g_cursor[i] = incl - v;
    if (tid == 1023) g_blocksum[b] = incl;
}

// single warp: exclusive scan of SCAN_BLOCKS block sums.
// Each lane owns CONSECUTIVE elements 2*lane and 2*lane+1 (ordering matters!).
__global__ void scan2_kernel() {
    int lane = threadIdx.x;  // 32 threads
    int i0 = 2 * lane, i1 = 2 * lane + 1;
    int v0 = (i0 < SCAN_BLOCKS) ? g_blocksum[i0] : 0;
    int v1 = (i1 < SCAN_BLOCKS) ? g_blocksum[i1] : 0;
    int s = v0 + v1;
    int x = s;
#pragma unroll
    for (int off = 1; off < 32; off <<= 1) {
        int t = __shfl_up_sync(0xffffffffu, x, off);
        if (lane >= off) x += t;
    }
    int excl = x - s;   // sum of all pairs before this lane
    if (i0 < SCAN_BLOCKS) g_blockoff[i0] = excl;
    if (i1 < SCAN_BLOCKS) g_blockoff[i1] = excl + v0;
    if (lane == 31) g_rowstart[N_NODES] = x;   // grand total
}

// add block offsets; produce rowstart + cursor
__global__ __launch_bounds__(1024) void scan3_kernel() {
    int i = blockIdx.x * 1024 + threadIdx.x;
    if (i >= N_NODES) return;
    int rs = g_cursor[i] + g_blockoff[blockIdx.x];
    g_rowstart[i] = rs;
    g_cursor[i]   = rs;
}

__global__ void place_kernel(const int* __restrict__ src, const int* __restrict__ dst) {
    int e = blockIdx.x * blockDim.x + threadIdx.x;
    if (e >= N_EDGES) return;
    int d = dst[e];
    int p = atomicAdd(&g_cursor[d], 1);
    g_srcsorted[p] = src[e];
}

// ---------------- 3) neighbor aggregation: h0 = x + sum x[src] ------------
__global__ void agg_kernel(int layer) {
    const float4* xin;
    int stride4;
    if (layer == 0) { xin = (const float4*)g_x0; stride4 = 32; }
    else            { xin = (const float4*)(g_xcat + (layer - 1) * HIDDEN); stride4 = 96; }
    int warp = threadIdx.x >> 5, lane = threadIdx.x & 31;
    int node = blockIdx.x * 4 + warp;
    if (node >= N_NODES) return;
    float4 acc = xin[(long)node * stride4 + lane];
    int s = g_rowstart[node], e = g_rowstart[node + 1];
    for (int j = s; j < e; j++) {
        int u = g_srcsorted[j];
        float4 v = xin[(long)u * stride4 + lane];
        acc.x += v.x; acc.y += v.y; acc.z += v.z; acc.w += v.w;
    }
    ((float4*)g_h0)[node * 32 + lane] = acc;
}

// ---------------- 4) fused GEMM (+bias,+relu[,+LN]) -----------------------
template <int MODE>
__global__ __launch_bounds__(256) void gemm_kernel(int layer,
                                                   const float* __restrict__ Wg,
                                                   const float* __restrict__ bg,
                                                   const float* __restrict__ lng,
                                                   const float* __restrict__ lnb) {
    extern __shared__ float sm[];
    float* Wsm = sm;                    // 128*128 floats (64 KB)
    float* Asm = sm + 128 * 128;        // 64*128 floats  (32 KB)
    const float* A = (MODE == 0) ? g_h0 : g_h1;

    int tid = threadIdx.x;
    int row0 = blockIdx.x * 64;

    const float4* W4 = (const float4*)Wg;
    float4* Wsm4 = (float4*)Wsm;
#pragma unroll
    for (int i = tid; i < 4096; i += 256) Wsm4[i] = W4[i];

    const float4* A4 = (const float4*)A;
    float4* Asm4 = (float4*)Asm;
#pragma unroll
    for (int i = tid; i < 2048; i += 256) {
        int r = i >> 5, c = i & 31;
        int gr = row0 + r;
        Asm4[i] = (gr < N_NODES) ? A4[gr * 32 + c] : make_float4(0.f, 0.f, 0.f, 0.f);
    }
    __syncthreads();

    int tx = tid & 31, ty = tid >> 5;
    float4 bv = ((const float4*)bg)[tx];
    unsigned long long acc[16];
#pragma unroll
    for (int r = 0; r < 8; r++) {
        acc[2 * r]     = pack2(bv.x, bv.y);
        acc[2 * r + 1] = pack2(bv.z, bv.w);
    }
    const ulonglong2* Wsm2 = (const ulonglong2*)Wsm;
    const float* Arow = Asm + ty * 8 * 128;

#pragma unroll 4
    for (int k0 = 0; k0 < 128; k0 += 4) {
        float4 a4[8];
#pragma unroll
        for (int r = 0; r < 8; r++)
            a4[r] = *(const float4*)(Arow + r * 128 + k0);
#pragma unroll
        for (int kk = 0; kk < 4; kk++) {
            ulonglong2 w = Wsm2[(k0 + kk) * 32 + tx];
#pragma unroll
            for (int r = 0; r < 8; r++) {
                float a = (kk == 0) ? a4[r].x : (kk == 1) ? a4[r].y
                         : (kk == 2) ? a4[r].z : a4[r].w;
                unsigned long long a2 = pack2(a, a);
                fma2(acc[2 * r],     a2, w.x);
                fma2(acc[2 * r + 1], a2, w.y);
            }
        }
    }

    if (MODE == 0) {
#pragma unroll
        for (int r = 0; r < 8; r++) {
            int row = row0 + ty * 8 + r;
            if (row >= N_NODES) continue;
            float v0, v1, v2, v3;
            unpack2(acc[2 * r], v0, v1);
            unpack2(acc[2 * r + 1], v2, v3);
            v0 = fmaxf(v0, 0.f); v1 = fmaxf(v1, 0.f);
            v2 = fmaxf(v2, 0.f); v3 = fmaxf(v3, 0.f);
            ((float4*)g_h1)[row * 32 + tx] = make_float4(v0, v1, v2, v3);
        }
    } else {
        float4 gv  = ((const float4*)lng)[tx];
        float4 bbv = ((const float4*)lnb)[tx];
#pragma unroll
        for (int r = 0; r < 8; r++) {
            float v0, v1, v2, v3;
            unpack2(acc[2 * r], v0, v1);
            unpack2(acc[2 * r + 1], v2, v3);
            v0 = fmaxf(v0, 0.f); v1 = fmaxf(v1, 0.f);
            v2 = fmaxf(v2, 0.f); v3 = fmaxf(v3, 0.f);
            float s = v0 + v1 + v2 + v3;
#pragma unroll
            for (int o = 16; o > 0; o >>= 1) s += __shfl_xor_sync(0xffffffffu, s, o);
            float mu = s * (1.f / 128.f);
            float d0 = v0 - mu, d1 = v1 - mu, d2 = v2 - mu, d3 = v3 - mu;
            float q = d0 * d0 + d1 * d1 + d2 * d2 + d3 * d3;
#pragma unroll
            for (int o = 16; o > 0; o >>= 1) q += __shfl_xor_sync(0xffffffffu, q, o);
            float rs = rsqrtf(q * (1.f / 128.f) + LN_EPS);
            float o0 = gv.x * d0 * rs + bbv.x;
            float o1 = gv.y * d1 * rs + bbv.y;
            float o2 = gv.z * d2 * rs + bbv.z;
            float o3 = gv.w * d3 * rs + bbv.w;
            int row = row0 + ty * 8 + r;
            if (row < N_NODES)
                ((float4*)g_xcat)[row * 96 + layer * 32 + tx] = make_float4(o0, o1, o2, o3);
        }
    }
}

// ---------------- 5) graph boundaries + mean pool -------------------------
__global__ void gstart_kernel(const int* __restrict__ batch) {
    int g = blockIdx.x * blockDim.x + threadIdx.x;
    if (g > N_GRAPHS) return;
    if (g == N_GRAPHS) { g_gstart[N_GRAPHS] = N_NODES; return; }
    int lo = 0, hi = N_NODES;
    while (lo < hi) {
        int mid = (lo + hi) >> 1;
        if (batch[mid] < g) lo = mid + 1; else hi = mid;
    }
    g_gstart[g] = lo;
}

__global__ void pool_kernel() {
    int g = blockIdx.x, t = threadIdx.x;   // 128 threads
    int s = g_gstart[g], e = g_gstart[g + 1];
    float a0 = 0.f, a1 = 0.f, a2 = 0.f;
    for (int n = s; n < e; n++) {
        const float* r = g_xcat + (long)n * 384;
        a0 += r[t]; a1 += r[128 + t]; a2 += r[256 + t];
    }
    float inv = 1.f / fmaxf((float)(e - s), 1.f);
    g_pooled[g * 384 + t]       = a0 * inv;
    g_pooled[g * 384 + 128 + t] = a1 * inv;
    g_pooled[g * 384 + 256 + t] = a2 * inv;
}

// ---------------- 6) MLP head ---------------------------------------------
__global__ void head_kernel(const float* __restrict__ l1W, const float* __restrict__ l1b,
                            const float* __restrict__ l2W, const float* __restrict__ l2b,
                            float* __restrict__ out) {
    __shared__ float prow[384];
    __shared__ float red[128];
    int g = blockIdx.x, t = threadIdx.x;   // 128 threads
    for (int i = t; i < 384; i += 128) prow[i] = g_pooled[g * 384 + i];
    __syncthreads();
    float s = l1b[t];
#pragma unroll 8
    for (int k = 0; k < 384; k++) s += prow[k] * l1W[k * 128 + t];
    s = fmaxf(s, 0.f);
    red[t] = s * l2W[t];
    __syncthreads();
    for (int off = 64; off > 0; off >>= 1) {
        if (t < off) red[t] += red[t + off];
        __syncthreads();
    }
    if (t == 0) out[g] = red[0] + l2b[0];
}

// ---------------- launch ---------------------------------------------------
extern "C" void kernel_launch(void* const* d_in, const int* in_sizes, int n_in,
                              void* d_out, int out_size) {
    const int*   z     = (const int*)d_in[0];
    const int*   ei    = (const int*)d_in[1];
    const int*   src   = ei;
    const int*   dst   = ei + N_EDGES;
    const int*   batch = (const int*)d_in[2];
    const float* ztab  = (const float*)d_in[3];
    const float* W1    = (const float*)d_in[4];
    const float* b1    = (const float*)d_in[5];
    const float* W2    = (const float*)d_in[6];
    const float* b2    = (const float*)d_in[7];
    const float* lng   = (const float*)d_in[8];
    const float* lnb   = (const float*)d_in[9];
    const float* l1W   = (const float*)d_in[10];
    const float* l1b   = (const float*)d_in[11];
    const float* l2W   = (const float*)d_in[12];
    const float* l2b   = (const float*)d_in[13];
    float* out = (float*)d_out;

    const int SMEM = 98304;  // 96 KB dynamic
    cudaFuncSetAttribute(gemm_kernel<0>, cudaFuncAttributeMaxDynamicSharedMemorySize, SMEM);
    cudaFuncSetAttribute(gemm_kernel<1>, cudaFuncAttributeMaxDynamicSharedMemorySize, SMEM);

    embed_kernel<<<(N_NODES * 32 + 255) / 256, 256>>>(z, (const float4*)ztab);
    zero_counts_kernel<<<(N_NODES + 255) / 256, 256>>>();
    count_kernel<<<(N_EDGES + 255) / 256, 256>>>(dst);
    scan1_kernel<<<SCAN_BLOCKS, 1024>>>();
    scan2_kernel<<<1, 32>>>();
    scan3_kernel<<<SCAN_BLOCKS, 1024>>>();
    place_kernel<<<(N_EDGES + 255) / 256, 256>>>(src, dst);

    const int GEMM_BLKS = (N_NODES + 63) / 64;
    for (int l = 0; l < N_LAYERS; l++) {
        agg_kernel<<<(N_NODES + 3) / 4, 128>>>(l);
        gemm_kernel<0><<<GEMM_BLKS, 256, SMEM>>>(l, W1 + l * 128 * 128, b1 + l * 128,
                                                 nullptr, nullptr);
        gemm_kernel<1><<<GEMM_BLKS, 256, SMEM>>>(l, W2 + l * 128 * 128, b2 + l * 128,
                                                 lng + l * 128, lnb + l * 128);
    }

    gstart_kernel<<<3, 256>>>(batch);
    pool_kernel<<<N_GRAPHS, 128>>>();
    head_kernel<<<N_GRAPHS, 128>>>(l1W, l1b, l2W, l2b, out);
}